// round 14
// baseline (speedup 1.0000x reference)
#include <cuda_runtime.h>

// Reference collapses: softmax(const(-9e15)) == uniform 1/N  =>  adj/a/e dead.
//   out[i,:] = relu( (colsum(h) @ W) / N )  -- one 64-float row broadcast 8192x.
// TWO kernels, NO interlock (graph edge is the sync):
//   K1: partial column sums + per-block projection -> g_pproj4 (32 KB)
//       *** loads forced to batch via asm volatile (MLP=8/thread) ***
//   K2: every block redundantly reduces the 32 KB payload, relu, writes slice.

#define N_ROWSC 8192
#define F_INC   512
#define F_OUTC  64
#define GRID    128
#define THREADS 1024
#define TOTAL_F4 (N_ROWSC * F_INC / 4)        // 1,048,576
#define STRIDE   (GRID * THREADS)             // 131,072 (multiple of 128)
#define LOADS_PT (TOTAL_F4 / STRIDE)          // 8 (exact)
#define OUT_F4   (N_ROWSC * F_OUTC / 4)       // 131,072 (1024 per block)

__device__ float4 g_pproj4[GRID * 16];        // 32 KB per-block projections

__device__ __forceinline__ void f4add(float4& a, const float4& v) {
    a.x += v.x; a.y += v.y; a.z += v.z; a.w += v.w;
}

// Volatile vector load: distinct asm statements keep program order and force
// ptxas to emit back-to-back LDG.128s into distinct registers (real MLP).
__device__ __forceinline__ float4 ldg_nc4(const float4* p) {
    float4 v;
    asm volatile("ld.global.nc.v4.f32 {%0,%1,%2,%3}, [%4];"
                 : "=f"(v.x), "=f"(v.y), "=f"(v.z), "=f"(v.w) : "l"(p));
    return v;
}

// ---- K1: colsum partials + per-block projection ----
__global__ __launch_bounds__(THREADS)
void k1_colsum_project(const float4* __restrict__ h4,
                       const float4* __restrict__ W4)
{
    __shared__ float4 s4[THREADS];            // 16 KB
    __shared__ float4 s4b[256];               // 4 KB
    __shared__ float  sf[F_INC];              // 2 KB

    const int t = threadIdx.x;
    const int b = blockIdx.x;

    // A: partial column sums; 8 LDGs issued back-to-back (forced batch).
    {
        const float4* p = h4 + (b * THREADS + t);   // colgroup = t & 127
        float4 v0 = ldg_nc4(p);
        float4 v1 = ldg_nc4(p + 1 * STRIDE);
        float4 v2 = ldg_nc4(p + 2 * STRIDE);
        float4 v3 = ldg_nc4(p + 3 * STRIDE);
        float4 v4 = ldg_nc4(p + 4 * STRIDE);
        float4 v5 = ldg_nc4(p + 5 * STRIDE);
        float4 v6 = ldg_nc4(p + 6 * STRIDE);
        float4 v7 = ldg_nc4(p + 7 * STRIDE);
        float4 acc = v0;                       // fixed order -> deterministic
        f4add(acc, v1); f4add(acc, v2); f4add(acc, v3);
        f4add(acc, v4); f4add(acc, v5); f4add(acc, v6); f4add(acc, v7);
        s4[t] = acc;
    }
    __syncthreads();
    if (t < 128) {                            // 8 partials per column group, fixed order
        float4 a = s4[t];
        #pragma unroll
        for (int j = 1; j < 8; ++j) f4add(a, s4[t + 128 * j]);
        sf[t * 4 + 0] = a.x; sf[t * 4 + 1] = a.y;
        sf[t * 4 + 2] = a.z; sf[t * 4 + 3] = a.w;
    }
    __syncthreads();

    // B: project colsum through W; i = t + j*1024 covers W exactly once.
    // colgroup(i) = i & 15 = t & 15 (const per thread); k(i) = i >> 4.
    // W loads batched the same way (break the fmaf-load serial chain).
    {
        const float4* wp = W4 + t;
        float4 w0 = ldg_nc4(wp);
        float4 w1 = ldg_nc4(wp + 1 * THREADS);
        float4 w2 = ldg_nc4(wp + 2 * THREADS);
        float4 w3 = ldg_nc4(wp + 3 * THREADS);
        float4 w4 = ldg_nc4(wp + 4 * THREADS);
        float4 w5 = ldg_nc4(wp + 5 * THREADS);
        float4 w6 = ldg_nc4(wp + 6 * THREADS);
        float4 w7 = ldg_nc4(wp + 7 * THREADS);
        const int k0 = t >> 4;
        float4 po = make_float4(0.f, 0.f, 0.f, 0.f);
        const float s0 = sf[k0 +   0], s1 = sf[k0 +  64],
                    s2 = sf[k0 + 128], s3 = sf[k0 + 192],
                    s4v = sf[k0 + 256], s5 = sf[k0 + 320],
                    s6 = sf[k0 + 384], s7 = sf[k0 + 448];
        po.x = fmaf(s0, w0.x, po.x); po.y = fmaf(s0, w0.y, po.y);
        po.z = fmaf(s0, w0.z, po.z); po.w = fmaf(s0, w0.w, po.w);
        po.x = fmaf(s1, w1.x, po.x); po.y = fmaf(s1, w1.y, po.y);
        po.z = fmaf(s1, w1.z, po.z); po.w = fmaf(s1, w1.w, po.w);
        po.x = fmaf(s2, w2.x, po.x); po.y = fmaf(s2, w2.y, po.y);
        po.z = fmaf(s2, w2.z, po.z); po.w = fmaf(s2, w2.w, po.w);
        po.x = fmaf(s3, w3.x, po.x); po.y = fmaf(s3, w3.y, po.y);
        po.z = fmaf(s3, w3.z, po.z); po.w = fmaf(s3, w3.w, po.w);
        po.x = fmaf(s4v, w4.x, po.x); po.y = fmaf(s4v, w4.y, po.y);
        po.z = fmaf(s4v, w4.z, po.z); po.w = fmaf(s4v, w4.w, po.w);
        po.x = fmaf(s5, w5.x, po.x); po.y = fmaf(s5, w5.y, po.y);
        po.z = fmaf(s5, w5.z, po.z); po.w = fmaf(s5, w5.w, po.w);
        po.x = fmaf(s6, w6.x, po.x); po.y = fmaf(s6, w6.y, po.y);
        po.z = fmaf(s6, w6.z, po.z); po.w = fmaf(s6, w6.w, po.w);
        po.x = fmaf(s7, w7.x, po.x); po.y = fmaf(s7, w7.y, po.y);
        po.z = fmaf(s7, w7.z, po.z); po.w = fmaf(s7, w7.w, po.w);
        s4[t] = po;
    }
    __syncthreads();
    if (t < 256) {                            // 1024 -> 256, same colgroup (t&15)
        float4 a = s4[t];
        f4add(a, s4[t + 256]); f4add(a, s4[t + 512]); f4add(a, s4[t + 768]);
        s4b[t] = a;
    }
    __syncthreads();
    if (t < 16) {                             // 256 -> 16, fixed order
        float4 a = s4b[t];
        #pragma unroll
        for (int m = 1; m < 16; ++m) f4add(a, s4b[t + 16 * m]);
        g_pproj4[b * 16 + t] = a;             // colgroup t
    }
}

// ---- K2: redundant per-block reduce of 32 KB payload + broadcast slice ----
// (byte-identical to R13 champion; isolate the K1 variable)
__global__ __launch_bounds__(THREADS)
void k2_reduce_broadcast(float4* __restrict__ out)
{
    __shared__ float4 s4[THREADS];            // 16 KB
    __shared__ float4 s4b[256];               // 4 KB
    __shared__ float4 srow4[16];              // 256 B

    const int t = threadIdx.x;
    const int b = blockIdx.x;

    {
        float4 a  = __ldcg(&g_pproj4[t]);            // colgroup = t & 15
        float4 v1 = __ldcg(&g_pproj4[t + 1024]);     // same colgroup
        f4add(a, v1);
        s4[t] = a;
    }
    __syncthreads();
    if (t < 256) {
        float4 a = s4[t];
        f4add(a, s4[t + 256]); f4add(a, s4[t + 512]); f4add(a, s4[t + 768]);
        s4b[t] = a;
    }
    __syncthreads();
    if (t < 16) {                             // 256 -> 16, fixed order
        float4 a = s4b[t];
        #pragma unroll
        for (int m = 1; m < 16; ++m) f4add(a, s4b[t + 16 * m]);
        const float inv = 1.0f / (float)N_ROWSC;
        a.x = fmaxf(a.x * inv, 0.f); a.y = fmaxf(a.y * inv, 0.f);
        a.z = fmaxf(a.z * inv, 0.f); a.w = fmaxf(a.w * inv, 0.f);
        srow4[t] = a;
    }
    __syncthreads();

    out[b * THREADS + t] = srow4[t & 15];     // 1024 % 16 == 0 -> colgroup = t & 15

    (void)OUT_F4;
}

extern "C" void kernel_launch(void* const* d_in, const int* in_sizes, int n_in,
                              void* d_out, int out_size) {
    (void)in_sizes; (void)n_in; (void)out_size;
    const float* h = (const float*)d_in[0];   // (8192, 512) fp32
    // d_in[1] = adj (8192,8192) -- dead code, never read
    const float* W = (const float*)d_in[2];   // (512, 64) fp32
    // d_in[3] = a (128,1)       -- dead code, never read
    float* out = (float*)d_out;               // (8192, 64) fp32

    k1_colsum_project<<<GRID, THREADS>>>((const float4*)h, (const float4*)W);
    k2_reduce_broadcast<<<GRID, THREADS>>>((float4*)out);
}